// round 4
// baseline (speedup 1.0000x reference)
#include <cuda_runtime.h>
#include <cuda_bf16.h>

#define N_NODES 10000
#define N_EDGES 320000
#define D 256
#define ALPHA 0.2f

// Scratch (no runtime allocation allowed)
__device__ float g_feats[N_NODES * D];   // 10.24 MB
__device__ float g_a1[N_NODES];
__device__ float g_a2[N_NODES];

// ---------------------------------------------------------------------------
// Kernel 1: feats = X @ W1 + b1   (M=10000, K=256, N=256)
// 64x64 tile, BK=16, 256 threads, 4x4 micro-tile.
// ---------------------------------------------------------------------------
__global__ void gemm_kernel(const float* __restrict__ X,
                            const float* __restrict__ W,
                            const float* __restrict__ b,
                            float* __restrict__ out)
{
    __shared__ float As[16][68];
    __shared__ float Bs[16][68];

    const int tid  = threadIdx.x;          // 0..255
    const int row0 = blockIdx.y * 64;
    const int col0 = blockIdx.x * 64;
    const int tx   = tid & 15;             // 0..15
    const int ty   = tid >> 4;             // 0..15

    // A-tile load mapping: one float4 per thread
    const int ar  = tid >> 2;              // 0..63 (tile row)
    const int ac4 = tid & 3;               // 0..3  (float4 slot in 16 cols)
    // B-tile load mapping
    const int br  = tid >> 4;              // 0..15 (k row)
    const int bc4 = tid & 15;              // 0..15 (float4 slot in 64 cols)

    float acc[4][4] = {};

    for (int k0 = 0; k0 < D; k0 += 16) {
        float4 av = make_float4(0.f, 0.f, 0.f, 0.f);
        const int garow = row0 + ar;
        if (garow < N_NODES)
            av = *(const float4*)(X + (size_t)garow * D + k0 + ac4 * 4);
        As[ac4 * 4 + 0][ar] = av.x;
        As[ac4 * 4 + 1][ar] = av.y;
        As[ac4 * 4 + 2][ar] = av.z;
        As[ac4 * 4 + 3][ar] = av.w;

        float4 bv = *(const float4*)(W + (size_t)(k0 + br) * D + col0 + bc4 * 4);
        *(float4*)&Bs[br][bc4 * 4] = bv;

        __syncthreads();

        #pragma unroll
        for (int k = 0; k < 16; k++) {
            float a[4], bb[4];
            #pragma unroll
            for (int i = 0; i < 4; i++) a[i]  = As[k][ty * 4 + i];
            #pragma unroll
            for (int j = 0; j < 4; j++) bb[j] = Bs[k][tx * 4 + j];
            #pragma unroll
            for (int i = 0; i < 4; i++)
                #pragma unroll
                for (int j = 0; j < 4; j++)
                    acc[i][j] += a[i] * bb[j];
        }
        __syncthreads();
    }

    #pragma unroll
    for (int i = 0; i < 4; i++) {
        const int r = row0 + ty * 4 + i;
        if (r < N_NODES) {
            #pragma unroll
            for (int j = 0; j < 4; j++) {
                const int c = col0 + tx * 4 + j;
                out[(size_t)r * D + c] = acc[i][j] + b[c];
            }
        }
    }
}

// ---------------------------------------------------------------------------
// Kernel 2: per-node attention dots  a1[n]=feats[n].Wa[:256], a2[n]=feats[n].Wa[256:]
// One warp per node.
// ---------------------------------------------------------------------------
__global__ void adot_kernel(const float* __restrict__ feats,
                            const float* __restrict__ Wa,
                            float* __restrict__ a1,
                            float* __restrict__ a2)
{
    const int warp = (blockIdx.x * blockDim.x + threadIdx.x) >> 5;
    const int lane = threadIdx.x & 31;
    if (warp >= N_NODES) return;

    const float* f = feats + (size_t)warp * D;
    float s1 = 0.f, s2 = 0.f;
    #pragma unroll
    for (int i = 0; i < 2; i++) {
        const int off = lane * 8 + i * 4;
        float4 fv = *(const float4*)(f + off);
        float4 w1 = *(const float4*)(Wa + off);
        float4 w2 = *(const float4*)(Wa + 256 + off);
        s1 += fv.x * w1.x + fv.y * w1.y + fv.z * w1.z + fv.w * w1.w;
        s2 += fv.x * w2.x + fv.y * w2.y + fv.z * w2.z + fv.w * w2.w;
    }
    #pragma unroll
    for (int o = 16; o > 0; o >>= 1) {
        s1 += __shfl_xor_sync(0xFFFFFFFFu, s1, o);
        s2 += __shfl_xor_sync(0xFFFFFFFFu, s2, o);
    }
    if (lane == 0) { a1[warp] = s1; a2[warp] = s2; }
}

// ---------------------------------------------------------------------------
// Kernel 3: per-node softmax-weighted aggregation.
// One block (256 threads) per node; src is sorted so the node's edges form a
// contiguous segment, found by binary search. Chunked exp in shared memory so
// each edge's expf is computed exactly once.
// out[i][t] = sum_e ex_e * feats[dst_e][t] / sum_e ex_e
// edges is int32 (JAX x64 disabled: astype(int64) silently yields int32).
// ---------------------------------------------------------------------------
__global__ void agg_kernel(const int* __restrict__ edges,
                           const float* __restrict__ feats,
                           const float* __restrict__ a1,
                           const float* __restrict__ a2,
                           const float* __restrict__ ba,
                           float* __restrict__ out)
{
    __shared__ float ex_sh[256];
    __shared__ int   dst_sh[256];
    __shared__ int   seg[2];

    const int i   = blockIdx.x;
    const int tid = threadIdx.x;

    if (tid == 0) {
        int lo = 0, hi = N_EDGES;
        while (lo < hi) {
            int mid = (lo + hi) >> 1;
            if (edges[2 * mid] < i) lo = mid + 1; else hi = mid;
        }
        seg[0] = lo;
        int lo2 = lo; hi = N_EDGES;
        while (lo2 < hi) {
            int mid = (lo2 + hi) >> 1;
            if (edges[2 * mid] < i + 1) lo2 = mid + 1; else hi = mid;
        }
        seg[1] = lo2;
    }
    __syncthreads();

    const int e0 = seg[0], e1 = seg[1];
    const float a1i = a1[i] + ba[0];

    float acc = 0.f, den = 0.f;

    for (int base = e0; base < e1; base += 256) {
        const int cnt = min(256, e1 - base);
        if (tid < cnt) {
            const int d = edges[2 * (base + tid) + 1];
            float s = a1i + a2[d];
            s = (s > 0.f) ? s : (ALPHA * s);
            ex_sh[tid]  = expf(s);
            dst_sh[tid] = d;
        }
        __syncthreads();
        for (int j = 0; j < cnt; j++) {
            const float e = ex_sh[j];
            den += e;
            acc += e * __ldg(feats + (size_t)dst_sh[j] * D + tid);
        }
        __syncthreads();
    }

    out[(size_t)i * D + tid] = (e1 > e0) ? (acc / den) : 0.f;
}

// ---------------------------------------------------------------------------
extern "C" void kernel_launch(void* const* d_in, const int* in_sizes, int n_in,
                              void* d_out, int out_size)
{
    const float* X   = (const float*)d_in[0];
    const int*   edg = (const int*)d_in[1];
    const float* W1  = (const float*)d_in[2];
    const float* b1  = (const float*)d_in[3];
    const float* Wa  = (const float*)d_in[4];
    const float* ba  = (const float*)d_in[5];
    float*       out = (float*)d_out;

    float* feats; cudaGetSymbolAddress((void**)&feats, g_feats);
    float* a1;    cudaGetSymbolAddress((void**)&a1,    g_a1);
    float* a2;    cudaGetSymbolAddress((void**)&a2,    g_a2);

    dim3 ggrid(D / 64, (N_NODES + 63) / 64);
    gemm_kernel<<<ggrid, 256>>>(X, W1, b1, feats);

    adot_kernel<<<(N_NODES * 32 + 255) / 256, 256>>>(feats, Wa, a1, a2);

    agg_kernel<<<N_NODES, 256>>>(edg, feats, a1, a2, ba, out);
}

// round 6
// speedup vs baseline: 1.3219x; 1.3219x over previous
#include <cuda_runtime.h>
#include <cuda_bf16.h>

#define N_NODES 10000
#define N_EDGES 320000
#define D 256
#define ALPHA 0.2f

// Scratch (no runtime allocation allowed)
__device__ float g_feats[N_NODES * D];   // 10.24 MB
__device__ float g_a1[N_NODES];
__device__ float g_a2[N_NODES];

// ---------------------------------------------------------------------------
// Kernel 1: feats = X @ W1 + b1   (M=10000, K=256, N=256)
// 128(M) x 64(N) tile, BK=16, 256 threads, 8x4 micro-tile,
// double-buffered shared memory with register prefetch.
// ---------------------------------------------------------------------------
__global__ __launch_bounds__(256) void gemm_kernel(const float* __restrict__ X,
                                                   const float* __restrict__ W,
                                                   const float* __restrict__ b,
                                                   float* __restrict__ out)
{
    __shared__ float As[2][16][132];   // [buf][k][row] (transposed)
    __shared__ float Bs[2][16][68];    // [buf][k][col]

    const int tid  = threadIdx.x;
    const int row0 = blockIdx.y * 128;
    const int col0 = blockIdx.x * 64;

    // A-tile loads: 128x16 = 512 float4; 2 per thread.
    const int ar  = tid >> 2;          // 0..63  (also ar+64)
    const int ac4 = tid & 3;           // 0..3   -> k = ac4*4..+3
    // B-tile loads: 16x64 = 256 float4; 1 per thread.
    const int br  = tid >> 4;          // 0..15  (k)
    const int bc4 = tid & 15;          // 0..15  -> col = bc4*4

    // compute mapping
    const int ty = tid >> 4;           // 0..15 -> rows ty*8..+7
    const int tx = tid & 15;           // 0..15 -> cols tx*4..+3

    // ---- preload tile 0 ----
    float4 a0 = make_float4(0.f,0.f,0.f,0.f), a1v = make_float4(0.f,0.f,0.f,0.f);
    if (row0 + ar      < N_NODES) a0  = *(const float4*)(X + (size_t)(row0+ar     )*D + ac4*4);
    if (row0 + ar + 64 < N_NODES) a1v = *(const float4*)(X + (size_t)(row0+ar+64  )*D + ac4*4);
    float4 bv = *(const float4*)(W + (size_t)br*D + col0 + bc4*4);

    As[0][ac4*4+0][ar]    = a0.x;  As[0][ac4*4+1][ar]    = a0.y;
    As[0][ac4*4+2][ar]    = a0.z;  As[0][ac4*4+3][ar]    = a0.w;
    As[0][ac4*4+0][ar+64] = a1v.x; As[0][ac4*4+1][ar+64] = a1v.y;
    As[0][ac4*4+2][ar+64] = a1v.z; As[0][ac4*4+3][ar+64] = a1v.w;
    *(float4*)&Bs[0][br][bc4*4] = bv;
    __syncthreads();

    float acc[8][4] = {};
    int cur = 0;

    for (int k0 = 16; k0 <= D; k0 += 16) {
        const bool has_next = (k0 < D);
        float4 na0, na1, nb;
        if (has_next) {
            na0 = make_float4(0.f,0.f,0.f,0.f);
            na1 = make_float4(0.f,0.f,0.f,0.f);
            if (row0 + ar      < N_NODES) na0 = *(const float4*)(X + (size_t)(row0+ar   )*D + k0 + ac4*4);
            if (row0 + ar + 64 < N_NODES) na1 = *(const float4*)(X + (size_t)(row0+ar+64)*D + k0 + ac4*4);
            nb = *(const float4*)(W + (size_t)(k0+br)*D + col0 + bc4*4);
        }

        #pragma unroll
        for (int k = 0; k < 16; k++) {
            float4 af0 = *(const float4*)&As[cur][k][ty*8];
            float4 af1 = *(const float4*)&As[cur][k][ty*8+4];
            float4 bf  = *(const float4*)&Bs[cur][k][tx*4];
            const float a[8] = {af0.x,af0.y,af0.z,af0.w,af1.x,af1.y,af1.z,af1.w};
            const float bb[4] = {bf.x,bf.y,bf.z,bf.w};
            #pragma unroll
            for (int i = 0; i < 8; i++)
                #pragma unroll
                for (int j = 0; j < 4; j++)
                    acc[i][j] += a[i] * bb[j];
        }

        if (has_next) {
            const int nxt = cur ^ 1;
            As[nxt][ac4*4+0][ar]    = na0.x; As[nxt][ac4*4+1][ar]    = na0.y;
            As[nxt][ac4*4+2][ar]    = na0.z; As[nxt][ac4*4+3][ar]    = na0.w;
            As[nxt][ac4*4+0][ar+64] = na1.x; As[nxt][ac4*4+1][ar+64] = na1.y;
            As[nxt][ac4*4+2][ar+64] = na1.z; As[nxt][ac4*4+3][ar+64] = na1.w;
            *(float4*)&Bs[nxt][br][bc4*4] = nb;
            __syncthreads();
            cur = nxt;
        }
    }

    const float4 bias = *(const float4*)(b + col0 + tx*4);
    #pragma unroll
    for (int i = 0; i < 8; i++) {
        const int r = row0 + ty*8 + i;
        if (r < N_NODES) {
            float4 o;
            o.x = acc[i][0] + bias.x;
            o.y = acc[i][1] + bias.y;
            o.z = acc[i][2] + bias.z;
            o.w = acc[i][3] + bias.w;
            *(float4*)(out + (size_t)r*D + col0 + tx*4) = o;
        }
    }
}

// ---------------------------------------------------------------------------
// Kernel 2: per-node attention dots  a1[n]=feats[n].Wa[:256], a2[n]=feats[n].Wa[256:]
// One warp per node.
// ---------------------------------------------------------------------------
__global__ void adot_kernel(const float* __restrict__ feats,
                            const float* __restrict__ Wa,
                            float* __restrict__ a1,
                            float* __restrict__ a2)
{
    const int warp = (blockIdx.x * blockDim.x + threadIdx.x) >> 5;
    const int lane = threadIdx.x & 31;
    if (warp >= N_NODES) return;

    const float* f = feats + (size_t)warp * D;
    float s1 = 0.f, s2 = 0.f;
    #pragma unroll
    for (int i = 0; i < 2; i++) {
        const int off = lane * 8 + i * 4;
        float4 fv = *(const float4*)(f + off);
        float4 w1 = *(const float4*)(Wa + off);
        float4 w2 = *(const float4*)(Wa + 256 + off);
        s1 += fv.x * w1.x + fv.y * w1.y + fv.z * w1.z + fv.w * w1.w;
        s2 += fv.x * w2.x + fv.y * w2.y + fv.z * w2.z + fv.w * w2.w;
    }
    #pragma unroll
    for (int o = 16; o > 0; o >>= 1) {
        s1 += __shfl_xor_sync(0xFFFFFFFFu, s1, o);
        s2 += __shfl_xor_sync(0xFFFFFFFFu, s2, o);
    }
    if (lane == 0) { a1[warp] = s1; a2[warp] = s2; }
}

// ---------------------------------------------------------------------------
// Kernel 3: per-node softmax-weighted aggregation.
// One block per node. Threads arranged as 4 edge-lanes x 64 col-lanes:
// each thread gathers float4 columns for its edge subset -> 4 edges in flight,
// 64 LDG.128 per edge instead of 256 LDG.32. Final cross-edge-lane reduction
// in shared memory.
// ---------------------------------------------------------------------------
__global__ __launch_bounds__(256) void agg_kernel(const int* __restrict__ edges,
                                                  const float* __restrict__ feats,
                                                  const float* __restrict__ a1,
                                                  const float* __restrict__ a2,
                                                  const float* __restrict__ ba,
                                                  float* __restrict__ out)
{
    __shared__ float  ex_sh[256];
    __shared__ int    dst_sh[256];
    __shared__ int    seg[2];
    __shared__ float4 racc[4][64];
    __shared__ float  dred[4];

    const int i   = blockIdx.x;
    const int tid = threadIdx.x;

    // lower_bound(src, i) and lower_bound(src, i+1) with two threads
    if (tid < 2) {
        const int target = i + tid;
        int lo = 0, hi = N_EDGES;
        while (lo < hi) {
            int mid = (lo + hi) >> 1;
            if (edges[2 * mid] < target) lo = mid + 1; else hi = mid;
        }
        seg[tid] = lo;
    }
    __syncthreads();

    const int e0 = seg[0], e1 = seg[1];
    const float a1i = a1[i] + ba[0];

    const int elane = tid >> 6;   // 0..3
    const int clane = tid & 63;   // 0..63 -> cols clane*4

    float4 acc = make_float4(0.f,0.f,0.f,0.f);
    float  den = 0.f;

    for (int base = e0; base < e1; base += 256) {
        const int cnt = min(256, e1 - base);
        if (tid < cnt) {
            const int d = edges[2 * (base + tid) + 1];
            float s = a1i + a2[d];
            s = (s > 0.f) ? s : (ALPHA * s);
            ex_sh[tid]  = expf(s);
            dst_sh[tid] = d;
        }
        __syncthreads();

        #pragma unroll 4
        for (int j = elane; j < cnt; j += 4) {
            const float e = ex_sh[j];
            const float4 f = *(const float4*)(feats + (size_t)dst_sh[j] * D + clane * 4);
            acc.x += e * f.x;
            acc.y += e * f.y;
            acc.z += e * f.z;
            acc.w += e * f.w;
            den   += e;
        }
        __syncthreads();
    }

    racc[elane][clane] = acc;
    if (clane == 0) dred[elane] = den;
    __syncthreads();

    if (elane == 0) {
        float4 t0 = racc[0][clane], t1 = racc[1][clane];
        float4 t2 = racc[2][clane], t3 = racc[3][clane];
        const float dtot = dred[0] + dred[1] + dred[2] + dred[3];
        float4 o = make_float4(0.f,0.f,0.f,0.f);
        if (e1 > e0) {
            const float inv = 1.f / dtot;
            o.x = (t0.x + t1.x + t2.x + t3.x) * inv;
            o.y = (t0.y + t1.y + t2.y + t3.y) * inv;
            o.z = (t0.z + t1.z + t2.z + t3.z) * inv;
            o.w = (t0.w + t1.w + t2.w + t3.w) * inv;
        }
        *(float4*)(out + (size_t)i * D + clane * 4) = o;
    }
}

// ---------------------------------------------------------------------------
extern "C" void kernel_launch(void* const* d_in, const int* in_sizes, int n_in,
                              void* d_out, int out_size)
{
    const float* X   = (const float*)d_in[0];
    const int*   edg = (const int*)d_in[1];
    const float* W1  = (const float*)d_in[2];
    const float* b1  = (const float*)d_in[3];
    const float* Wa  = (const float*)d_in[4];
    const float* ba  = (const float*)d_in[5];
    float*       out = (float*)d_out;

    float* feats; cudaGetSymbolAddress((void**)&feats, g_feats);
    float* a1;    cudaGetSymbolAddress((void**)&a1,    g_a1);
    float* a2;    cudaGetSymbolAddress((void**)&a2,    g_a2);

    dim3 ggrid(D / 64, (N_NODES + 127) / 128);   // 4 x 79
    gemm_kernel<<<ggrid, 256>>>(X, W1, b1, feats);

    adot_kernel<<<(N_NODES * 32 + 255) / 256, 256>>>(feats, Wa, a1, a2);

    agg_kernel<<<N_NODES, 256>>>(edg, feats, a1, a2, ba, out);
}

// round 7
// speedup vs baseline: 1.4970x; 1.1324x over previous
#include <cuda_runtime.h>
#include <cuda_fp16.h>
#include <cuda_bf16.h>

#define N_NODES 10000
#define N_EDGES 320000
#define D 256
#define ALPHA 0.2f

// Scratch (no runtime allocation allowed)
__device__ float  g_feats[N_NODES * D];     // 10.24 MB fp32 (for adot)
__device__ __half g_feats_h[N_NODES * D];   // 5.12 MB fp16 (for agg gather)
__device__ float  g_a1[N_NODES];
__device__ float  g_a2[N_NODES];
__device__ int    g_rowptr[N_NODES + 1];

// ---------------------------------------------------------------------------
// Kernel 1: feats = X @ W1 + b1   (M=10000, K=256, N=256)
// 128(M) x 128(N) tile, BK=16, 256 threads, 8x8 micro-tile, double-buffered.
// Columns split as [tx*4] and [64+tx*4] for conflict-free LDS.128.
// Epilogue writes fp32 and fp16 copies.
// ---------------------------------------------------------------------------
__global__ __launch_bounds__(256) void gemm_kernel(const float* __restrict__ X,
                                                   const float* __restrict__ W,
                                                   const float* __restrict__ b,
                                                   float* __restrict__ out,
                                                   __half* __restrict__ outh)
{
    __shared__ float As[2][16][132];   // [buf][k][row] (transposed)
    __shared__ float Bs[2][16][132];   // [buf][k][col]

    const int tid  = threadIdx.x;
    const int row0 = blockIdx.y * 128;
    const int col0 = blockIdx.x * 128;

    // A-tile loads: 128x16 = 512 float4; 2 per thread (rows ar, ar+64).
    const int ar  = tid >> 2;          // 0..63
    const int ac4 = tid & 3;           // k = ac4*4..+3
    // B-tile loads: 16x128 = 512 float4; 2 per thread (cols bc4*4, 64+bc4*4).
    const int br  = tid >> 4;          // 0..15 (k)
    const int bc4 = tid & 15;

    // compute mapping: rows ty*8..+7, cols tx*4..+3 and 64+tx*4..+3
    const int ty = tid >> 4;           // 0..15
    const int tx = tid & 15;           // 0..15

    // ---- preload tile 0 ----
    float4 pa0 = make_float4(0.f,0.f,0.f,0.f), pa1 = make_float4(0.f,0.f,0.f,0.f);
    if (row0 + ar      < N_NODES) pa0 = *(const float4*)(X + (size_t)(row0+ar   )*D + ac4*4);
    if (row0 + ar + 64 < N_NODES) pa1 = *(const float4*)(X + (size_t)(row0+ar+64)*D + ac4*4);
    float4 pb0 = *(const float4*)(W + (size_t)br*D + col0 + bc4*4);
    float4 pb1 = *(const float4*)(W + (size_t)br*D + col0 + 64 + bc4*4);

    As[0][ac4*4+0][ar]    = pa0.x; As[0][ac4*4+1][ar]    = pa0.y;
    As[0][ac4*4+2][ar]    = pa0.z; As[0][ac4*4+3][ar]    = pa0.w;
    As[0][ac4*4+0][ar+64] = pa1.x; As[0][ac4*4+1][ar+64] = pa1.y;
    As[0][ac4*4+2][ar+64] = pa1.z; As[0][ac4*4+3][ar+64] = pa1.w;
    *(float4*)&Bs[0][br][bc4*4]      = pb0;
    *(float4*)&Bs[0][br][64 + bc4*4] = pb1;
    __syncthreads();

    float acc[8][8] = {};
    int cur = 0;

    for (int k0 = 16; k0 <= D; k0 += 16) {
        const bool has_next = (k0 < D);
        float4 na0, na1, nb0, nb1;
        if (has_next) {
            na0 = make_float4(0.f,0.f,0.f,0.f);
            na1 = make_float4(0.f,0.f,0.f,0.f);
            if (row0 + ar      < N_NODES) na0 = *(const float4*)(X + (size_t)(row0+ar   )*D + k0 + ac4*4);
            if (row0 + ar + 64 < N_NODES) na1 = *(const float4*)(X + (size_t)(row0+ar+64)*D + k0 + ac4*4);
            nb0 = *(const float4*)(W + (size_t)(k0+br)*D + col0 + bc4*4);
            nb1 = *(const float4*)(W + (size_t)(k0+br)*D + col0 + 64 + bc4*4);
        }

        #pragma unroll
        for (int k = 0; k < 16; k++) {
            float4 af0 = *(const float4*)&As[cur][k][ty*8];
            float4 af1 = *(const float4*)&As[cur][k][ty*8+4];
            float4 bf0 = *(const float4*)&Bs[cur][k][tx*4];
            float4 bf1 = *(const float4*)&Bs[cur][k][64 + tx*4];
            const float a[8]  = {af0.x,af0.y,af0.z,af0.w,af1.x,af1.y,af1.z,af1.w};
            const float bb[8] = {bf0.x,bf0.y,bf0.z,bf0.w,bf1.x,bf1.y,bf1.z,bf1.w};
            #pragma unroll
            for (int i = 0; i < 8; i++)
                #pragma unroll
                for (int j = 0; j < 8; j++)
                    acc[i][j] += a[i] * bb[j];
        }

        if (has_next) {
            const int nxt = cur ^ 1;
            As[nxt][ac4*4+0][ar]    = na0.x; As[nxt][ac4*4+1][ar]    = na0.y;
            As[nxt][ac4*4+2][ar]    = na0.z; As[nxt][ac4*4+3][ar]    = na0.w;
            As[nxt][ac4*4+0][ar+64] = na1.x; As[nxt][ac4*4+1][ar+64] = na1.y;
            As[nxt][ac4*4+2][ar+64] = na1.z; As[nxt][ac4*4+3][ar+64] = na1.w;
            *(float4*)&Bs[nxt][br][bc4*4]      = nb0;
            *(float4*)&Bs[nxt][br][64 + bc4*4] = nb1;
            __syncthreads();
            cur = nxt;
        }
    }

    const float4 biasA = *(const float4*)(b + col0 + tx*4);
    const float4 biasB = *(const float4*)(b + col0 + 64 + tx*4);
    #pragma unroll
    for (int i = 0; i < 8; i++) {
        const int r = row0 + ty*8 + i;
        if (r < N_NODES) {
            float4 oA, oB;
            oA.x = acc[i][0] + biasA.x; oA.y = acc[i][1] + biasA.y;
            oA.z = acc[i][2] + biasA.z; oA.w = acc[i][3] + biasA.w;
            oB.x = acc[i][4] + biasB.x; oB.y = acc[i][5] + biasB.y;
            oB.z = acc[i][6] + biasB.z; oB.w = acc[i][7] + biasB.w;
            const int cA = col0 + tx*4, cB = col0 + 64 + tx*4;
            *(float4*)(out + (size_t)r*D + cA) = oA;
            *(float4*)(out + (size_t)r*D + cB) = oB;

            union { __half2 h[2]; uint2 u; } pA, pB;
            pA.h[0] = __floats2half2_rn(oA.x, oA.y);
            pA.h[1] = __floats2half2_rn(oA.z, oA.w);
            pB.h[0] = __floats2half2_rn(oB.x, oB.y);
            pB.h[1] = __floats2half2_rn(oB.z, oB.w);
            *(uint2*)(outh + (size_t)r*D + cA) = pA.u;
            *(uint2*)(outh + (size_t)r*D + cB) = pB.u;
        }
    }
}

// ---------------------------------------------------------------------------
// Kernel 2: per-node attention dots (fp32 feats): a1[n], a2[n]. One warp/node.
// ---------------------------------------------------------------------------
__global__ void adot_kernel(const float* __restrict__ feats,
                            const float* __restrict__ Wa,
                            float* __restrict__ a1,
                            float* __restrict__ a2)
{
    const int warp = (blockIdx.x * blockDim.x + threadIdx.x) >> 5;
    const int lane = threadIdx.x & 31;
    if (warp >= N_NODES) return;

    const float* f = feats + (size_t)warp * D;
    float s1 = 0.f, s2 = 0.f;
    #pragma unroll
    for (int i = 0; i < 2; i++) {
        const int off = lane * 8 + i * 4;
        float4 fv = *(const float4*)(f + off);
        float4 w1 = *(const float4*)(Wa + off);
        float4 w2 = *(const float4*)(Wa + 256 + off);
        s1 += fv.x * w1.x + fv.y * w1.y + fv.z * w1.z + fv.w * w1.w;
        s2 += fv.x * w2.x + fv.y * w2.y + fv.z * w2.z + fv.w * w2.w;
    }
    #pragma unroll
    for (int o = 16; o > 0; o >>= 1) {
        s1 += __shfl_xor_sync(0xFFFFFFFFu, s1, o);
        s2 += __shfl_xor_sync(0xFFFFFFFFu, s2, o);
    }
    if (lane == 0) { a1[warp] = s1; a2[warp] = s2; }
}

// ---------------------------------------------------------------------------
// Kernel 2b: CSR row pointers from sorted src. rowptr[i] = lower_bound(src, i).
// ---------------------------------------------------------------------------
__global__ void rowptr_kernel(const int* __restrict__ edges,
                              int* __restrict__ rowptr)
{
    const int e = blockIdx.x * blockDim.x + threadIdx.x;
    if (e >= N_EDGES) return;
    const int s    = edges[2 * e];
    const int prev = (e == 0) ? -1 : edges[2 * (e - 1)];
    for (int j = prev + 1; j <= s; j++) rowptr[j] = e;
    if (e == N_EDGES - 1)
        for (int j = s + 1; j <= N_NODES; j++) rowptr[j] = N_EDGES;
}

// ---------------------------------------------------------------------------
// Kernel 3: per-node softmax-weighted aggregation over fp16 feature table.
// One block per node; 8 edge-lanes x 32 col-lanes, each thread gathers
// uint4 = 8 halfs per edge. fp32 accumulate, cross-lane reduce in shared.
// ---------------------------------------------------------------------------
__global__ __launch_bounds__(256) void agg_kernel(const int* __restrict__ edges,
                                                  const __half* __restrict__ featsh,
                                                  const float* __restrict__ a1,
                                                  const float* __restrict__ a2,
                                                  const float* __restrict__ ba,
                                                  const int* __restrict__ rowptr,
                                                  float* __restrict__ out)
{
    __shared__ float ex_sh[256];
    __shared__ int   dst_sh[256];
    __shared__ float racc[8][32][8];   // [elane][clane][col]
    __shared__ float dred[8];

    const int i   = blockIdx.x;
    const int tid = threadIdx.x;

    const int e0 = rowptr[i];
    const int e1 = rowptr[i + 1];
    const float a1i = a1[i] + ba[0];

    const int elane = tid >> 5;   // 0..7
    const int clane = tid & 31;   // cols clane*8 .. +7

    float acc[8] = {};
    float den = 0.f;

    for (int base = e0; base < e1; base += 256) {
        const int cnt = min(256, e1 - base);
        if (tid < cnt) {
            const int d = edges[2 * (base + tid) + 1];
            float s = a1i + a2[d];
            s = (s > 0.f) ? s : (ALPHA * s);
            ex_sh[tid]  = expf(s);
            dst_sh[tid] = d;
        }
        __syncthreads();

        #pragma unroll 4
        for (int j = elane; j < cnt; j += 8) {
            const float e = ex_sh[j];
            const uint4 v = *(const uint4*)(featsh + (size_t)dst_sh[j] * D + clane * 8);
            const float2 f0 = __half22float2(*(const __half2*)&v.x);
            const float2 f1 = __half22float2(*(const __half2*)&v.y);
            const float2 f2 = __half22float2(*(const __half2*)&v.z);
            const float2 f3 = __half22float2(*(const __half2*)&v.w);
            acc[0] += e * f0.x; acc[1] += e * f0.y;
            acc[2] += e * f1.x; acc[3] += e * f1.y;
            acc[4] += e * f2.x; acc[5] += e * f2.y;
            acc[6] += e * f3.x; acc[7] += e * f3.y;
            den    += e;
        }
        __syncthreads();
    }

    *(float4*)&racc[elane][clane][0] = make_float4(acc[0], acc[1], acc[2], acc[3]);
    *(float4*)&racc[elane][clane][4] = make_float4(acc[4], acc[5], acc[6], acc[7]);
    if (clane == 0) dred[elane] = den;
    __syncthreads();

    if (elane == 0) {
        float s[8] = {};
        #pragma unroll
        for (int e2 = 0; e2 < 8; e2++) {
            #pragma unroll
            for (int c = 0; c < 8; c++) s[c] += racc[e2][clane][c];
        }
        float dtot = 0.f;
        #pragma unroll
        for (int e2 = 0; e2 < 8; e2++) dtot += dred[e2];

        const float inv = (e1 > e0) ? (1.f / dtot) : 0.f;
        float4 o0 = make_float4(s[0]*inv, s[1]*inv, s[2]*inv, s[3]*inv);
        float4 o1 = make_float4(s[4]*inv, s[5]*inv, s[6]*inv, s[7]*inv);
        *(float4*)(out + (size_t)i * D + clane * 8)     = o0;
        *(float4*)(out + (size_t)i * D + clane * 8 + 4) = o1;
    }
}

// ---------------------------------------------------------------------------
extern "C" void kernel_launch(void* const* d_in, const int* in_sizes, int n_in,
                              void* d_out, int out_size)
{
    const float* X   = (const float*)d_in[0];
    const int*   edg = (const int*)d_in[1];
    const float* W1  = (const float*)d_in[2];
    const float* b1  = (const float*)d_in[3];
    const float* Wa  = (const float*)d_in[4];
    const float* ba  = (const float*)d_in[5];
    float*       out = (float*)d_out;

    float*  feats;  cudaGetSymbolAddress((void**)&feats,  g_feats);
    __half* featsh; cudaGetSymbolAddress((void**)&featsh, g_feats_h);
    float*  a1;     cudaGetSymbolAddress((void**)&a1,     g_a1);
    float*  a2;     cudaGetSymbolAddress((void**)&a2,     g_a2);
    int*    rowptr; cudaGetSymbolAddress((void**)&rowptr, g_rowptr);

    rowptr_kernel<<<(N_EDGES + 255) / 256, 256>>>(edg, rowptr);

    dim3 ggrid(D / 128, (N_NODES + 127) / 128);   // 2 x 79
    gemm_kernel<<<ggrid, 256>>>(X, W1, b1, feats, featsh);

    adot_kernel<<<(N_NODES * 32 + 255) / 256, 256>>>(feats, Wa, a1, a2);

    agg_kernel<<<N_NODES, 256>>>(edg, featsh, a1, a2, ba, rowptr, out);
}

// round 9
// speedup vs baseline: 2.7676x; 1.8488x over previous
#include <cuda_runtime.h>
#include <cuda_fp16.h>
#include <cstdint>

#define N_NODES 10000
#define N_EDGES 320000
#define D 256
#define ALPHA 0.2f

// ---------------- scratch (no runtime allocation allowed) ------------------
__device__ __half g_feats_h[N_NODES * D];   // 5.12 MB fp16 gather table
__device__ float  g_a1[N_NODES];
__device__ float  g_a2[N_NODES];
__device__ float  g_u1[D];
__device__ float  g_u2[D];
__device__ float  g_c12[2];
__device__ int    g_rowptr[N_NODES + 1];

__device__ __forceinline__ uint32_t smem_u32(const void* p) {
    uint32_t a;
    asm("{ .reg .u64 t; cvta.to.shared.u64 t, %1; cvt.u32.u64 %0, t; }" : "=r"(a) : "l"(p));
    return a;
}

#define LDMATRIX_X4(r0,r1,r2,r3, addr)                                      \
    asm volatile("ldmatrix.sync.aligned.m8n8.x4.shared.b16 {%0,%1,%2,%3}, [%4];" \
        : "=r"(r0),"=r"(r1),"=r"(r2),"=r"(r3) : "r"(addr))

#define LDMATRIX_X4_T(r0,r1,r2,r3, addr)                                    \
    asm volatile("ldmatrix.sync.aligned.m8n8.x4.trans.shared.b16 {%0,%1,%2,%3}, [%4];" \
        : "=r"(r0),"=r"(r1),"=r"(r2),"=r"(r3) : "r"(addr))

#define MMA_16816(c, a, b0, b1)                                             \
    asm volatile("mma.sync.aligned.m16n8k16.row.col.f32.f16.f16.f32 "       \
        "{%0,%1,%2,%3}, {%4,%5,%6,%7}, {%8,%9}, {%0,%1,%2,%3};"             \
        : "+f"((c)[0]),"+f"((c)[1]),"+f"((c)[2]),"+f"((c)[3])               \
        : "r"((a)[0]),"r"((a)[1]),"r"((a)[2]),"r"((a)[3]), "r"(b0),"r"(b1))

// ---------------------------------------------------------------------------
// HMMA GEMM: feats_h = fp16(X @ W1 + b1).  CTA tile 128(M) x 128(N), BK=32.
// 8 warps: 4(m) x 2(n); warp tile 32 x 64 = 2 x 8 m16n8k16 tiles.
// A staged [m][k] k-contig; B staged [k][n] n-contig (W native layout).
// ---------------------------------------------------------------------------
__global__ __launch_bounds__(256) void gemm_mma_kernel(const float* __restrict__ X,
                                                       const float* __restrict__ W,
                                                       const float* __restrict__ b,
                                                       __half* __restrict__ outh)
{
    __shared__ __half As[128][40];    // 128 rows x 32 k (+8 pad)
    __shared__ __half Bs[32][136];    // 32 k x 128 n (+8 pad)

    const int tid  = threadIdx.x;
    const int wid  = tid >> 5;
    const int lane = tid & 31;
    const int row0 = blockIdx.y * 128;
    const int col0 = blockIdx.x * 128;

    const int wm0 = (wid & 3) * 32;   // warp m offset in tile
    const int wn0 = (wid >> 2) * 64;  // warp n offset in tile

    // global->smem load mapping
    const int ar  = tid >> 1;         // 0..127 (A row)
    const int ak0 = (tid & 1) * 16;   // A k chunk
    const int brw = tid >> 3;         // 0..31  (B k-row)
    const int bc0 = (tid & 7) * 16;   // B col chunk

    float acc[2][8][4] = {};

    for (int k0 = 0; k0 < D; k0 += 32) {
        // ---- A tile: 16 floats per thread -> fp16 ----
        {
            const int r = row0 + ar;
            float4 f[4];
            if (r < N_NODES) {
                const float* src = X + (size_t)r * D + k0 + ak0;
                f[0] = *(const float4*)(src + 0);
                f[1] = *(const float4*)(src + 4);
                f[2] = *(const float4*)(src + 8);
                f[3] = *(const float4*)(src + 12);
            } else {
                f[0]=f[1]=f[2]=f[3]=make_float4(0.f,0.f,0.f,0.f);
            }
            union { __half2 h[8]; uint4 u[2]; } pk;
            #pragma unroll
            for (int i = 0; i < 4; i++) {
                pk.h[i*2+0] = __floats2half2_rn(f[i].x, f[i].y);
                pk.h[i*2+1] = __floats2half2_rn(f[i].z, f[i].w);
            }
            uint4* dst = (uint4*)&As[ar][ak0];
            dst[0] = pk.u[0];
            dst[1] = pk.u[1];
        }
        // ---- B tile: 16 floats per thread -> fp16 ----
        {
            const float* src = W + (size_t)(k0 + brw) * D + col0 + bc0;
            float4 f[4];
            f[0] = *(const float4*)(src + 0);
            f[1] = *(const float4*)(src + 4);
            f[2] = *(const float4*)(src + 8);
            f[3] = *(const float4*)(src + 12);
            union { __half2 h[8]; uint4 u[2]; } pk;
            #pragma unroll
            for (int i = 0; i < 4; i++) {
                pk.h[i*2+0] = __floats2half2_rn(f[i].x, f[i].y);
                pk.h[i*2+1] = __floats2half2_rn(f[i].z, f[i].w);
            }
            uint4* dst = (uint4*)&Bs[brw][bc0];
            dst[0] = pk.u[0];
            dst[1] = pk.u[1];
        }
        __syncthreads();

        // ---- MMA over two k16 groups ----
        #pragma unroll
        for (int kg = 0; kg < 2; kg++) {
            uint32_t afr[2][4];
            #pragma unroll
            for (int mi = 0; mi < 2; mi++) {
                const uint32_t addr = smem_u32(
                    &As[wm0 + mi*16 + (lane & 15)][kg*16 + ((lane >> 4) << 3)]);
                LDMATRIX_X4(afr[mi][0], afr[mi][1], afr[mi][2], afr[mi][3], addr);
            }
            uint32_t bfr[4][4];
            #pragma unroll
            for (int ng = 0; ng < 4; ng++) {
                const uint32_t addr = smem_u32(
                    &Bs[kg*16 + (lane & 15)][wn0 + ng*16 + ((lane >> 4) << 3)]);
                LDMATRIX_X4_T(bfr[ng][0], bfr[ng][1], bfr[ng][2], bfr[ng][3], addr);
            }
            #pragma unroll
            for (int mi = 0; mi < 2; mi++)
                #pragma unroll
                for (int ni = 0; ni < 8; ni++)
                    MMA_16816(acc[mi][ni], afr[mi],
                              bfr[ni >> 1][(ni & 1) * 2 + 0],
                              bfr[ni >> 1][(ni & 1) * 2 + 1]);
        }
        __syncthreads();
    }

    // ---- epilogue: add bias, write fp16 ----
    const int gr = lane >> 2;          // 0..7
    const int gc = (lane & 3) * 2;
    #pragma unroll
    for (int mi = 0; mi < 2; mi++) {
        const int ra = row0 + wm0 + mi*16 + gr;
        const int rb = ra + 8;
        #pragma unroll
        for (int ni = 0; ni < 8; ni++) {
            const int col = col0 + wn0 + ni*8 + gc;
            const float bx = b[col], by = b[col + 1];
            if (ra < N_NODES)
                *(__half2*)(outh + (size_t)ra * D + col) =
                    __floats2half2_rn(acc[mi][ni][0] + bx, acc[mi][ni][1] + by);
            if (rb < N_NODES)
                *(__half2*)(outh + (size_t)rb * D + col) =
                    __floats2half2_rn(acc[mi][ni][2] + bx, acc[mi][ni][3] + by);
        }
    }
}

// ---------------------------------------------------------------------------
// u1 = W1 @ wa1, u2 = W1 @ wa2, c1 = b1.wa1, c2 = b1.wa2
// ---------------------------------------------------------------------------
__global__ void u_kernel(const float* __restrict__ W,
                         const float* __restrict__ b1,
                         const float* __restrict__ Wa,
                         float* __restrict__ u1, float* __restrict__ u2,
                         float* __restrict__ c12)
{
    const int w = (blockIdx.x * blockDim.x + threadIdx.x) >> 5;
    const int lane = threadIdx.x & 31;
    if (w >= D + 1) return;

    const float* vec = (w < D) ? (W + (size_t)w * D) : b1;
    float s1 = 0.f, s2 = 0.f;
    #pragma unroll
    for (int i = 0; i < 2; i++) {
        const int off = lane * 8 + i * 4;
        const float4 fv = *(const float4*)(vec + off);
        const float4 w1 = *(const float4*)(Wa + off);
        const float4 w2 = *(const float4*)(Wa + D + off);
        s1 += fv.x*w1.x + fv.y*w1.y + fv.z*w1.z + fv.w*w1.w;
        s2 += fv.x*w2.x + fv.y*w2.y + fv.z*w2.z + fv.w*w2.w;
    }
    #pragma unroll
    for (int o = 16; o > 0; o >>= 1) {
        s1 += __shfl_xor_sync(0xFFFFFFFFu, s1, o);
        s2 += __shfl_xor_sync(0xFFFFFFFFu, s2, o);
    }
    if (lane == 0) {
        if (w < D) { u1[w] = s1; u2[w] = s2; }
        else       { c12[0] = s1; c12[1] = s2; }
    }
}

// ---------------------------------------------------------------------------
// a1[n] = X[n].u1 + c1 ;  a2[n] = X[n].u2 + c2   (exact fp32 score path)
// ---------------------------------------------------------------------------
__global__ void adot_kernel(const float* __restrict__ X,
                            const float* __restrict__ u1,
                            const float* __restrict__ u2,
                            const float* __restrict__ c12,
                            float* __restrict__ a1, float* __restrict__ a2)
{
    const int n = (blockIdx.x * blockDim.x + threadIdx.x) >> 5;
    const int lane = threadIdx.x & 31;
    if (n >= N_NODES) return;

    const float* x = X + (size_t)n * D;
    float s1 = 0.f, s2 = 0.f;
    #pragma unroll
    for (int i = 0; i < 2; i++) {
        const int off = lane * 8 + i * 4;
        const float4 xv = *(const float4*)(x + off);
        const float4 v1 = *(const float4*)(u1 + off);
        const float4 v2 = *(const float4*)(u2 + off);
        s1 += xv.x*v1.x + xv.y*v1.y + xv.z*v1.z + xv.w*v1.w;
        s2 += xv.x*v2.x + xv.y*v2.y + xv.z*v2.z + xv.w*v2.w;
    }
    #pragma unroll
    for (int o = 16; o > 0; o >>= 1) {
        s1 += __shfl_xor_sync(0xFFFFFFFFu, s1, o);
        s2 += __shfl_xor_sync(0xFFFFFFFFu, s2, o);
    }
    if (lane == 0) { a1[n] = s1 + c12[0]; a2[n] = s2 + c12[1]; }
}

// ---------------------------------------------------------------------------
// CSR row pointers from sorted src
// ---------------------------------------------------------------------------
__global__ void rowptr_kernel(const int* __restrict__ edges,
                              int* __restrict__ rowptr)
{
    const int e = blockIdx.x * blockDim.x + threadIdx.x;
    if (e >= N_EDGES) return;
    const int s    = edges[2 * e];
    const int prev = (e == 0) ? -1 : edges[2 * (e - 1)];
    for (int j = prev + 1; j <= s; j++) rowptr[j] = e;
    if (e == N_EDGES - 1)
        for (int j = s + 1; j <= N_NODES; j++) rowptr[j] = N_EDGES;
}

// ---------------------------------------------------------------------------
// Aggregation: one WARP per node. Chunks of 32 edges; lane j computes
// exp(score) for edge j, then shfl-broadcast (ex, dst); every lane
// accumulates its 8 columns (16B fp16 gather per edge per lane).
// ---------------------------------------------------------------------------
__global__ __launch_bounds__(256) void agg_kernel(const int* __restrict__ edges,
                                                  const __half* __restrict__ featsh,
                                                  const float* __restrict__ a1,
                                                  const float* __restrict__ a2,
                                                  const float* __restrict__ ba,
                                                  const int* __restrict__ rowptr,
                                                  float* __restrict__ out)
{
    const int i    = (blockIdx.x * blockDim.x + threadIdx.x) >> 5;
    const int lane = threadIdx.x & 31;
    if (i >= N_NODES) return;

    const int e0 = rowptr[i];
    const int e1 = rowptr[i + 1];
    const float a1i = a1[i] + ba[0];

    float acc[8] = {};
    float den = 0.f;

    for (int base = e0; base < e1; base += 32) {
        const int idx = base + lane;
        const bool valid = (idx < e1);
        const int d = valid ? edges[2 * idx + 1] : 0;
        float ex = 0.f;
        if (valid) {
            float s = a1i + a2[d];
            s = (s > 0.f) ? s : (ALPHA * s);
            ex = expf(s);
        }
        const int cnt = min(32, e1 - base);
        #pragma unroll 4
        for (int j = 0; j < cnt; j++) {
            const float e = __shfl_sync(0xFFFFFFFFu, ex, j);
            const int  dd = __shfl_sync(0xFFFFFFFFu, d,  j);
            const uint4 v = *(const uint4*)(featsh + (size_t)dd * D + lane * 8);
            const float2 f0 = __half22float2(*(const __half2*)&v.x);
            const float2 f1 = __half22float2(*(const __half2*)&v.y);
            const float2 f2 = __half22float2(*(const __half2*)&v.z);
            const float2 f3 = __half22float2(*(const __half2*)&v.w);
            acc[0] += e * f0.x; acc[1] += e * f0.y;
            acc[2] += e * f1.x; acc[3] += e * f1.y;
            acc[4] += e * f2.x; acc[5] += e * f2.y;
            acc[6] += e * f3.x; acc[7] += e * f3.y;
            den    += e;
        }
    }

    const float inv = (e1 > e0) ? (1.f / den) : 0.f;
    float4 o0 = make_float4(acc[0]*inv, acc[1]*inv, acc[2]*inv, acc[3]*inv);
    float4 o1 = make_float4(acc[4]*inv, acc[5]*inv, acc[6]*inv, acc[7]*inv);
    *(float4*)(out + (size_t)i * D + lane * 8)     = o0;
    *(float4*)(out + (size_t)i * D + lane * 8 + 4) = o1;
}

// ---------------------------------------------------------------------------
extern "C" void kernel_launch(void* const* d_in, const int* in_sizes, int n_in,
                              void* d_out, int out_size)
{
    const float* X   = (const float*)d_in[0];
    const int*   edg = (const int*)d_in[1];
    const float* W1  = (const float*)d_in[2];
    const float* b1  = (const float*)d_in[3];
    const float* Wa  = (const float*)d_in[4];
    const float* ba  = (const float*)d_in[5];
    float*       out = (float*)d_out;

    __half* featsh; cudaGetSymbolAddress((void**)&featsh, g_feats_h);
    float*  a1;     cudaGetSymbolAddress((void**)&a1,     g_a1);
    float*  a2;     cudaGetSymbolAddress((void**)&a2,     g_a2);
    float*  u1;     cudaGetSymbolAddress((void**)&u1,     g_u1);
    float*  u2;     cudaGetSymbolAddress((void**)&u2,     g_u2);
    float*  c12;    cudaGetSymbolAddress((void**)&c12,    g_c12);
    int*    rowptr; cudaGetSymbolAddress((void**)&rowptr, g_rowptr);

    rowptr_kernel<<<(N_EDGES + 255) / 256, 256>>>(edg, rowptr);
    u_kernel<<<((D + 1) * 32 + 255) / 256, 256>>>(W1, b1, Wa, u1, u2, c12);
    adot_kernel<<<(N_NODES * 32 + 255) / 256, 256>>>(X, u1, u2, c12, a1, a2);

    dim3 ggrid(D / 128, (N_NODES + 127) / 128);   // 2 x 79
    gemm_mma_kernel<<<ggrid, 256>>>(X, W1, b1, featsh);

    agg_kernel<<<(N_NODES * 32 + 255) / 256, 256>>>(edg, featsh, a1, a2, ba, rowptr, out);
}

// round 10
// speedup vs baseline: 3.0707x; 1.1095x over previous
#include <cuda_runtime.h>
#include <cuda_fp16.h>
#include <cstdint>

#define N_NODES 10000
#define N_EDGES 320000
#define D 256
#define ALPHA 0.2f

// ---------------- scratch (no runtime allocation allowed) ------------------
__device__ __half g_feats_h[N_NODES * D];   // 5.12 MB fp16 gather table
__device__ float  g_a1[N_NODES];
__device__ float  g_a2[N_NODES];
__device__ float  g_u1[D];
__device__ float  g_u2[D];
__device__ float  g_c12[2];
__device__ int    g_rowptr[N_NODES + 1];

__device__ __forceinline__ uint32_t smem_u32(const void* p) {
    uint32_t a;
    asm("{ .reg .u64 t; cvta.to.shared.u64 t, %1; cvt.u32.u64 %0, t; }" : "=r"(a) : "l"(p));
    return a;
}

#define LDMATRIX_X4(r0,r1,r2,r3, addr)                                      \
    asm volatile("ldmatrix.sync.aligned.m8n8.x4.shared.b16 {%0,%1,%2,%3}, [%4];" \
        : "=r"(r0),"=r"(r1),"=r"(r2),"=r"(r3) : "r"(addr))

#define LDMATRIX_X4_T(r0,r1,r2,r3, addr)                                    \
    asm volatile("ldmatrix.sync.aligned.m8n8.x4.trans.shared.b16 {%0,%1,%2,%3}, [%4];" \
        : "=r"(r0),"=r"(r1),"=r"(r2),"=r"(r3) : "r"(addr))

#define MMA_16816(c, a, b0, b1)                                             \
    asm volatile("mma.sync.aligned.m16n8k16.row.col.f32.f16.f16.f32 "       \
        "{%0,%1,%2,%3}, {%4,%5,%6,%7}, {%8,%9}, {%0,%1,%2,%3};"             \
        : "+f"((c)[0]),"+f"((c)[1]),"+f"((c)[2]),"+f"((c)[3])               \
        : "r"((a)[0]),"r"((a)[1]),"r"((a)[2]),"r"((a)[3]), "r"(b0),"r"(b1))

// ---------------------------------------------------------------------------
// HMMA GEMM + fused adot.
// feats_h = fp16(X @ W1 + b1); CTAs with blockIdx.x==0 also compute
// a1[r] = X[r].u1 + c1, a2[r] = X[r].u2 + c2 (exact fp32) during A loads.
// CTA tile 128(M) x 64(N), BK=32, 8 warps = 4(m) x 2(n), warp tile 32x32.
// Register-prefetch software pipeline over the 8 k-iterations.
// ---------------------------------------------------------------------------
__global__ __launch_bounds__(256) void gemm_mma_kernel(const float* __restrict__ X,
                                                       const float* __restrict__ W,
                                                       const float* __restrict__ b,
                                                       const float* __restrict__ u1,
                                                       const float* __restrict__ u2,
                                                       const float* __restrict__ c12,
                                                       __half* __restrict__ outh,
                                                       float* __restrict__ a1,
                                                       float* __restrict__ a2)
{
    __shared__ __half As[128][40];    // 128 m x 32 k (+8 pad)
    __shared__ __half Bs[32][72];     // 32 k x 64 n (+8 pad)

    const int tid  = threadIdx.x;
    const int wid  = tid >> 5;
    const int lane = tid & 31;
    const int row0 = blockIdx.y * 128;
    const int col0 = blockIdx.x * 64;
    const bool do_adot = (blockIdx.x == 0);

    const int wm0 = (wid & 3) * 32;
    const int wn0 = (wid >> 2) * 32;

    // A loads: row ar = tid>>1 (0..127), k chunk (tid&1)*16
    const int ar  = tid >> 1;
    const int ak0 = (tid & 1) * 16;
    const bool arow_ok = (row0 + ar) < N_NODES;
    // B loads: k-row tid>>3 (0..31), col chunk (tid&7)*8
    const int brw = tid >> 3;
    const int bc0 = (tid & 7) * 8;

    float acc[2][4][4] = {};
    float s1 = 0.f, s2 = 0.f;

    float4 fA[4], fB[2];

    // ---- prefetch iter 0 ----
    {
        if (arow_ok) {
            const float* src = X + (size_t)(row0 + ar) * D + ak0;
            fA[0] = *(const float4*)(src + 0);
            fA[1] = *(const float4*)(src + 4);
            fA[2] = *(const float4*)(src + 8);
            fA[3] = *(const float4*)(src + 12);
        } else {
            fA[0]=fA[1]=fA[2]=fA[3]=make_float4(0.f,0.f,0.f,0.f);
        }
        const float* bsrc = W + (size_t)brw * D + col0 + bc0;
        fB[0] = *(const float4*)(bsrc + 0);
        fB[1] = *(const float4*)(bsrc + 4);
    }

    #pragma unroll 1
    for (int it = 0; it < 8; it++) {
        const int k0 = it * 32;

        // ---- adot accumulate on current A regs (exact fp32) ----
        if (do_adot) {
            const float* v1 = u1 + k0 + ak0;
            const float* v2 = u2 + k0 + ak0;
            #pragma unroll
            for (int i = 0; i < 4; i++) {
                const float4 q1 = *(const float4*)(v1 + i * 4);
                const float4 q2 = *(const float4*)(v2 + i * 4);
                s1 += fA[i].x*q1.x + fA[i].y*q1.y + fA[i].z*q1.z + fA[i].w*q1.w;
                s2 += fA[i].x*q2.x + fA[i].y*q2.y + fA[i].z*q2.z + fA[i].w*q2.w;
            }
        }

        // ---- store current regs to smem (fp16) ----
        {
            union { __half2 h[8]; uint4 u[2]; } pk;
            #pragma unroll
            for (int i = 0; i < 4; i++) {
                pk.h[i*2+0] = __floats2half2_rn(fA[i].x, fA[i].y);
                pk.h[i*2+1] = __floats2half2_rn(fA[i].z, fA[i].w);
            }
            uint4* dst = (uint4*)&As[ar][ak0];
            dst[0] = pk.u[0]; dst[1] = pk.u[1];

            union { __half2 h[4]; uint4 u; } pb;
            pb.h[0] = __floats2half2_rn(fB[0].x, fB[0].y);
            pb.h[1] = __floats2half2_rn(fB[0].z, fB[0].w);
            pb.h[2] = __floats2half2_rn(fB[1].x, fB[1].y);
            pb.h[3] = __floats2half2_rn(fB[1].z, fB[1].w);
            *(uint4*)&Bs[brw][bc0] = pb.u;
        }
        __syncthreads();

        // ---- prefetch next iter (overlaps with MMA below) ----
        if (it < 7) {
            const int kn = k0 + 32;
            if (arow_ok) {
                const float* src = X + (size_t)(row0 + ar) * D + kn + ak0;
                fA[0] = *(const float4*)(src + 0);
                fA[1] = *(const float4*)(src + 4);
                fA[2] = *(const float4*)(src + 8);
                fA[3] = *(const float4*)(src + 12);
            }
            const float* bsrc = W + (size_t)(kn + brw) * D + col0 + bc0;
            fB[0] = *(const float4*)(bsrc + 0);
            fB[1] = *(const float4*)(bsrc + 4);
        }

        // ---- MMA over two k16 groups ----
        #pragma unroll
        for (int kg = 0; kg < 2; kg++) {
            uint32_t afr[2][4];
            #pragma unroll
            for (int mi = 0; mi < 2; mi++) {
                const uint32_t addr = smem_u32(
                    &As[wm0 + mi*16 + (lane & 15)][kg*16 + ((lane >> 4) << 3)]);
                LDMATRIX_X4(afr[mi][0], afr[mi][1], afr[mi][2], afr[mi][3], addr);
            }
            uint32_t bfr[2][4];
            #pragma unroll
            for (int ng = 0; ng < 2; ng++) {
                const uint32_t addr = smem_u32(
                    &Bs[kg*16 + (lane & 15)][wn0 + ng*16 + ((lane >> 4) << 3)]);
                LDMATRIX_X4_T(bfr[ng][0], bfr[ng][1], bfr[ng][2], bfr[ng][3], addr);
            }
            #pragma unroll
            for (int mi = 0; mi < 2; mi++)
                #pragma unroll
                for (int ni = 0; ni < 4; ni++)
                    MMA_16816(acc[mi][ni], afr[mi],
                              bfr[ni >> 1][(ni & 1) * 2 + 0],
                              bfr[ni >> 1][(ni & 1) * 2 + 1]);
        }
        __syncthreads();
    }

    // ---- adot writeback: pair-reduce (tid, tid^1) via shfl ----
    if (do_adot) {
        s1 += __shfl_xor_sync(0xFFFFFFFFu, s1, 1);
        s2 += __shfl_xor_sync(0xFFFFFFFFu, s2, 1);
        if ((tid & 1) == 0 && arow_ok) {
            a1[row0 + ar] = s1 + c12[0];
            a2[row0 + ar] = s2 + c12[1];
        }
    }

    // ---- epilogue: add bias, write fp16 ----
    const int gr = lane >> 2;
    const int gc = (lane & 3) * 2;
    #pragma unroll
    for (int mi = 0; mi < 2; mi++) {
        const int ra = row0 + wm0 + mi*16 + gr;
        const int rb = ra + 8;
        #pragma unroll
        for (int ni = 0; ni < 4; ni++) {
            const int col = col0 + wn0 + ni*8 + gc;
            const float bx = b[col], by = b[col + 1];
            if (ra < N_NODES)
                *(__half2*)(outh + (size_t)ra * D + col) =
                    __floats2half2_rn(acc[mi][ni][0] + bx, acc[mi][ni][1] + by);
            if (rb < N_NODES)
                *(__half2*)(outh + (size_t)rb * D + col) =
                    __floats2half2_rn(acc[mi][ni][2] + bx, acc[mi][ni][3] + by);
        }
    }
}

// ---------------------------------------------------------------------------
// u1 = W1 @ wa1, u2 = W1 @ wa2, c1 = b1.wa1, c2 = b1.wa2
// ---------------------------------------------------------------------------
__global__ void u_kernel(const float* __restrict__ W,
                         const float* __restrict__ b1,
                         const float* __restrict__ Wa,
                         float* __restrict__ u1, float* __restrict__ u2,
                         float* __restrict__ c12)
{
    const int w = (blockIdx.x * blockDim.x + threadIdx.x) >> 5;
    const int lane = threadIdx.x & 31;
    if (w >= D + 1) return;

    const float* vec = (w < D) ? (W + (size_t)w * D) : b1;
    float s1 = 0.f, s2 = 0.f;
    #pragma unroll
    for (int i = 0; i < 2; i++) {
        const int off = lane * 8 + i * 4;
        const float4 fv = *(const float4*)(vec + off);
        const float4 w1 = *(const float4*)(Wa + off);
        const float4 w2 = *(const float4*)(Wa + D + off);
        s1 += fv.x*w1.x + fv.y*w1.y + fv.z*w1.z + fv.w*w1.w;
        s2 += fv.x*w2.x + fv.y*w2.y + fv.z*w2.z + fv.w*w2.w;
    }
    #pragma unroll
    for (int o = 16; o > 0; o >>= 1) {
        s1 += __shfl_xor_sync(0xFFFFFFFFu, s1, o);
        s2 += __shfl_xor_sync(0xFFFFFFFFu, s2, o);
    }
    if (lane == 0) {
        if (w < D) { u1[w] = s1; u2[w] = s2; }
        else       { c12[0] = s1; c12[1] = s2; }
    }
}

// ---------------------------------------------------------------------------
// CSR row pointers from sorted src
// ---------------------------------------------------------------------------
__global__ void rowptr_kernel(const int* __restrict__ edges,
                              int* __restrict__ rowptr)
{
    const int e = blockIdx.x * blockDim.x + threadIdx.x;
    if (e >= N_EDGES) return;
    const int s    = edges[2 * e];
    const int prev = (e == 0) ? -1 : edges[2 * (e - 1)];
    for (int j = prev + 1; j <= s; j++) rowptr[j] = e;
    if (e == N_EDGES - 1)
        for (int j = s + 1; j <= N_NODES; j++) rowptr[j] = N_EDGES;
}

// ---------------------------------------------------------------------------
// Aggregation: one WARP per node. Chunks of 32 edges; lane j computes
// exp(score) for edge j, then shfl-broadcast (ex, dst); every lane
// accumulates its 8 columns (16B fp16 gather per edge per lane).
// ---------------------------------------------------------------------------
__global__ __launch_bounds__(256) void agg_kernel(const int* __restrict__ edges,
                                                  const __half* __restrict__ featsh,
                                                  const float* __restrict__ a1,
                                                  const float* __restrict__ a2,
                                                  const float* __restrict__ ba,
                                                  const int* __restrict__ rowptr,
                                                  float* __restrict__ out)
{
    const int i    = (blockIdx.x * blockDim.x + threadIdx.x) >> 5;
    const int lane = threadIdx.x & 31;
    if (i >= N_NODES) return;

    const int e0 = rowptr[i];
    const int e1 = rowptr[i + 1];
    const float a1i = a1[i] + ba[0];

    float acc[8] = {};
    float den = 0.f;

    for (int base = e0; base < e1; base += 32) {
        const int idx = base + lane;
        const bool valid = (idx < e1);
        const int d = valid ? edges[2 * idx + 1] : 0;
        float ex = 0.f;
        if (valid) {
            float s = a1i + a2[d];
            s = (s > 0.f) ? s : (ALPHA * s);
            ex = expf(s);
        }
        const int cnt = min(32, e1 - base);
        #pragma unroll 4
        for (int j = 0; j < cnt; j++) {
            const float e = __shfl_sync(0xFFFFFFFFu, ex, j);
            const int  dd = __shfl_sync(0xFFFFFFFFu, d,  j);
            const uint4 v = *(const uint4*)(featsh + (size_t)dd * D + lane * 8);
            const float2 f0 = __half22float2(*(const __half2*)&v.x);
            const float2 f1 = __half22float2(*(const __half2*)&v.y);
            const float2 f2 = __half22float2(*(const __half2*)&v.z);
            const float2 f3 = __half22float2(*(const __half2*)&v.w);
            acc[0] += e * f0.x; acc[1] += e * f0.y;
            acc[2] += e * f1.x; acc[3] += e * f1.y;
            acc[4] += e * f2.x; acc[5] += e * f2.y;
            acc[6] += e * f3.x; acc[7] += e * f3.y;
            den    += e;
        }
    }

    const float inv = (e1 > e0) ? (1.f / den) : 0.f;
    float4 o0 = make_float4(acc[0]*inv, acc[1]*inv, acc[2]*inv, acc[3]*inv);
    float4 o1 = make_float4(acc[4]*inv, acc[5]*inv, acc[6]*inv, acc[7]*inv);
    *(float4*)(out + (size_t)i * D + lane * 8)     = o0;
    *(float4*)(out + (size_t)i * D + lane * 8 + 4) = o1;
}

// ---------------------------------------------------------------------------
extern "C" void kernel_launch(void* const* d_in, const int* in_sizes, int n_in,
                              void* d_out, int out_size)
{
    const float* X   = (const float*)d_in[0];
    const int*   edg = (const int*)d_in[1];
    const float* W1  = (const float*)d_in[2];
    const float* b1  = (const float*)d_in[3];
    const float* Wa  = (const float*)d_in[4];
    const float* ba  = (const float*)d_in[5];
    float*       out = (float*)d_out;

    __half* featsh; cudaGetSymbolAddress((void**)&featsh, g_feats_h);
    float*  a1;     cudaGetSymbolAddress((void**)&a1,     g_a1);
    float*  a2;     cudaGetSymbolAddress((void**)&a2,     g_a2);
    float*  u1;     cudaGetSymbolAddress((void**)&u1,     g_u1);
    float*  u2;     cudaGetSymbolAddress((void**)&u2,     g_u2);
    float*  c12;    cudaGetSymbolAddress((void**)&c12,    g_c12);
    int*    rowptr; cudaGetSymbolAddress((void**)&rowptr, g_rowptr);

    rowptr_kernel<<<(N_EDGES + 255) / 256, 256>>>(edg, rowptr);
    u_kernel<<<((D + 1) * 32 + 255) / 256, 256>>>(W1, b1, Wa, u1, u2, c12);

    dim3 ggrid(D / 64, (N_NODES + 127) / 128);   // 4 x 79 = 316 CTAs
    gemm_mma_kernel<<<ggrid, 256>>>(X, W1, b1, u1, u2, c12, featsh, a1, a2);

    agg_kernel<<<(N_NODES * 32 + 255) / 256, 256>>>(edg, featsh, a1, a2, ba, rowptr, out);
}

// round 11
// speedup vs baseline: 3.0943x; 1.0077x over previous
#include <cuda_runtime.h>
#include <cuda_fp16.h>
#include <cstdint>

#define N_NODES 10000
#define N_EDGES 320000
#define D 256
#define ALPHA 0.2f

// ---------------- scratch (no runtime allocation allowed) ------------------
__device__ __half g_feats_h[N_NODES * D];   // 5.12 MB fp16 gather table
__device__ float  g_a1[N_NODES];
__device__ float  g_a2[N_NODES];
__device__ float  g_u1[D];
__device__ float  g_u2[D];
__device__ float  g_c12[2];
__device__ int    g_rowptr[N_NODES + 1];

__device__ __forceinline__ uint32_t smem_u32(const void* p) {
    uint32_t a;
    asm("{ .reg .u64 t; cvta.to.shared.u64 t, %1; cvt.u32.u64 %0, t; }" : "=r"(a) : "l"(p));
    return a;
}

#define LDMATRIX_X4(r0,r1,r2,r3, addr)                                      \
    asm volatile("ldmatrix.sync.aligned.m8n8.x4.shared.b16 {%0,%1,%2,%3}, [%4];" \
        : "=r"(r0),"=r"(r1),"=r"(r2),"=r"(r3) : "r"(addr))

#define LDMATRIX_X4_T(r0,r1,r2,r3, addr)                                    \
    asm volatile("ldmatrix.sync.aligned.m8n8.x4.trans.shared.b16 {%0,%1,%2,%3}, [%4];" \
        : "=r"(r0),"=r"(r1),"=r"(r2),"=r"(r3) : "r"(addr))

#define MMA_16816(c, a, b0, b1)                                             \
    asm volatile("mma.sync.aligned.m16n8k16.row.col.f32.f16.f16.f32 "       \
        "{%0,%1,%2,%3}, {%4,%5,%6,%7}, {%8,%9}, {%0,%1,%2,%3};"             \
        : "+f"((c)[0]),"+f"((c)[1]),"+f"((c)[2]),"+f"((c)[3])               \
        : "r"((a)[0]),"r"((a)[1]),"r"((a)[2]),"r"((a)[3]), "r"(b0),"r"(b1))

// ---------------------------------------------------------------------------
// HMMA GEMM + fused adot (unchanged from round 10 — it works).
// ---------------------------------------------------------------------------
__global__ __launch_bounds__(256) void gemm_mma_kernel(const float* __restrict__ X,
                                                       const float* __restrict__ W,
                                                       const float* __restrict__ b,
                                                       const float* __restrict__ u1,
                                                       const float* __restrict__ u2,
                                                       const float* __restrict__ c12,
                                                       __half* __restrict__ outh,
                                                       float* __restrict__ a1,
                                                       float* __restrict__ a2)
{
    __shared__ __half As[128][40];
    __shared__ __half Bs[32][72];

    const int tid  = threadIdx.x;
    const int wid  = tid >> 5;
    const int lane = tid & 31;
    const int row0 = blockIdx.y * 128;
    const int col0 = blockIdx.x * 64;
    const bool do_adot = (blockIdx.x == 0);

    const int wm0 = (wid & 3) * 32;
    const int wn0 = (wid >> 2) * 32;

    const int ar  = tid >> 1;
    const int ak0 = (tid & 1) * 16;
    const bool arow_ok = (row0 + ar) < N_NODES;
    const int brw = tid >> 3;
    const int bc0 = (tid & 7) * 8;

    float acc[2][4][4] = {};
    float s1 = 0.f, s2 = 0.f;
    float4 fA[4], fB[2];

    {
        if (arow_ok) {
            const float* src = X + (size_t)(row0 + ar) * D + ak0;
            fA[0] = *(const float4*)(src + 0);
            fA[1] = *(const float4*)(src + 4);
            fA[2] = *(const float4*)(src + 8);
            fA[3] = *(const float4*)(src + 12);
        } else {
            fA[0]=fA[1]=fA[2]=fA[3]=make_float4(0.f,0.f,0.f,0.f);
        }
        const float* bsrc = W + (size_t)brw * D + col0 + bc0;
        fB[0] = *(const float4*)(bsrc + 0);
        fB[1] = *(const float4*)(bsrc + 4);
    }

    #pragma unroll 1
    for (int it = 0; it < 8; it++) {
        const int k0 = it * 32;

        if (do_adot) {
            const float* v1 = u1 + k0 + ak0;
            const float* v2 = u2 + k0 + ak0;
            #pragma unroll
            for (int i = 0; i < 4; i++) {
                const float4 q1 = *(const float4*)(v1 + i * 4);
                const float4 q2 = *(const float4*)(v2 + i * 4);
                s1 += fA[i].x*q1.x + fA[i].y*q1.y + fA[i].z*q1.z + fA[i].w*q1.w;
                s2 += fA[i].x*q2.x + fA[i].y*q2.y + fA[i].z*q2.z + fA[i].w*q2.w;
            }
        }

        {
            union { __half2 h[8]; uint4 u[2]; } pk;
            #pragma unroll
            for (int i = 0; i < 4; i++) {
                pk.h[i*2+0] = __floats2half2_rn(fA[i].x, fA[i].y);
                pk.h[i*2+1] = __floats2half2_rn(fA[i].z, fA[i].w);
            }
            uint4* dst = (uint4*)&As[ar][ak0];
            dst[0] = pk.u[0]; dst[1] = pk.u[1];

            union { __half2 h[4]; uint4 u; } pb;
            pb.h[0] = __floats2half2_rn(fB[0].x, fB[0].y);
            pb.h[1] = __floats2half2_rn(fB[0].z, fB[0].w);
            pb.h[2] = __floats2half2_rn(fB[1].x, fB[1].y);
            pb.h[3] = __floats2half2_rn(fB[1].z, fB[1].w);
            *(uint4*)&Bs[brw][bc0] = pb.u;
        }
        __syncthreads();

        if (it < 7) {
            const int kn = k0 + 32;
            if (arow_ok) {
                const float* src = X + (size_t)(row0 + ar) * D + kn + ak0;
                fA[0] = *(const float4*)(src + 0);
                fA[1] = *(const float4*)(src + 4);
                fA[2] = *(const float4*)(src + 8);
                fA[3] = *(const float4*)(src + 12);
            }
            const float* bsrc = W + (size_t)(kn + brw) * D + col0 + bc0;
            fB[0] = *(const float4*)(bsrc + 0);
            fB[1] = *(const float4*)(bsrc + 4);
        }

        #pragma unroll
        for (int kg = 0; kg < 2; kg++) {
            uint32_t afr[2][4];
            #pragma unroll
            for (int mi = 0; mi < 2; mi++) {
                const uint32_t addr = smem_u32(
                    &As[wm0 + mi*16 + (lane & 15)][kg*16 + ((lane >> 4) << 3)]);
                LDMATRIX_X4(afr[mi][0], afr[mi][1], afr[mi][2], afr[mi][3], addr);
            }
            uint32_t bfr[2][4];
            #pragma unroll
            for (int ng = 0; ng < 2; ng++) {
                const uint32_t addr = smem_u32(
                    &Bs[kg*16 + (lane & 15)][wn0 + ng*16 + ((lane >> 4) << 3)]);
                LDMATRIX_X4_T(bfr[ng][0], bfr[ng][1], bfr[ng][2], bfr[ng][3], addr);
            }
            #pragma unroll
            for (int mi = 0; mi < 2; mi++)
                #pragma unroll
                for (int ni = 0; ni < 4; ni++)
                    MMA_16816(acc[mi][ni], afr[mi],
                              bfr[ni >> 1][(ni & 1) * 2 + 0],
                              bfr[ni >> 1][(ni & 1) * 2 + 1]);
        }
        __syncthreads();
    }

    if (do_adot) {
        s1 += __shfl_xor_sync(0xFFFFFFFFu, s1, 1);
        s2 += __shfl_xor_sync(0xFFFFFFFFu, s2, 1);
        if ((tid & 1) == 0 && arow_ok) {
            a1[row0 + ar] = s1 + c12[0];
            a2[row0 + ar] = s2 + c12[1];
        }
    }

    const int gr = lane >> 2;
    const int gc = (lane & 3) * 2;
    #pragma unroll
    for (int mi = 0; mi < 2; mi++) {
        const int ra = row0 + wm0 + mi*16 + gr;
        const int rb = ra + 8;
        #pragma unroll
        for (int ni = 0; ni < 4; ni++) {
            const int col = col0 + wn0 + ni*8 + gc;
            const float bx = b[col], by = b[col + 1];
            if (ra < N_NODES)
                *(__half2*)(outh + (size_t)ra * D + col) =
                    __floats2half2_rn(acc[mi][ni][0] + bx, acc[mi][ni][1] + by);
            if (rb < N_NODES)
                *(__half2*)(outh + (size_t)rb * D + col) =
                    __floats2half2_rn(acc[mi][ni][2] + bx, acc[mi][ni][3] + by);
        }
    }
}

// ---------------------------------------------------------------------------
__global__ void u_kernel(const float* __restrict__ W,
                         const float* __restrict__ b1,
                         const float* __restrict__ Wa,
                         float* __restrict__ u1, float* __restrict__ u2,
                         float* __restrict__ c12)
{
    const int w = (blockIdx.x * blockDim.x + threadIdx.x) >> 5;
    const int lane = threadIdx.x & 31;
    if (w >= D + 1) return;

    const float* vec = (w < D) ? (W + (size_t)w * D) : b1;
    float s1 = 0.f, s2 = 0.f;
    #pragma unroll
    for (int i = 0; i < 2; i++) {
        const int off = lane * 8 + i * 4;
        const float4 fv = *(const float4*)(vec + off);
        const float4 w1 = *(const float4*)(Wa + off);
        const float4 w2 = *(const float4*)(Wa + D + off);
        s1 += fv.x*w1.x + fv.y*w1.y + fv.z*w1.z + fv.w*w1.w;
        s2 += fv.x*w2.x + fv.y*w2.y + fv.z*w2.z + fv.w*w2.w;
    }
    #pragma unroll
    for (int o = 16; o > 0; o >>= 1) {
        s1 += __shfl_xor_sync(0xFFFFFFFFu, s1, o);
        s2 += __shfl_xor_sync(0xFFFFFFFFu, s2, o);
    }
    if (lane == 0) {
        if (w < D) { u1[w] = s1; u2[w] = s2; }
        else       { c12[0] = s1; c12[1] = s2; }
    }
}

// ---------------------------------------------------------------------------
__global__ void rowptr_kernel(const int* __restrict__ edges,
                              int* __restrict__ rowptr)
{
    const int e = blockIdx.x * blockDim.x + threadIdx.x;
    if (e >= N_EDGES) return;
    const int s    = edges[2 * e];
    const int prev = (e == 0) ? -1 : edges[2 * (e - 1)];
    for (int j = prev + 1; j <= s; j++) rowptr[j] = e;
    if (e == N_EDGES - 1)
        for (int j = s + 1; j <= N_NODES; j++) rowptr[j] = N_EDGES;
}

// ---------------------------------------------------------------------------
// Aggregation v2: TWO warps per node, edge-range split; 4 nodes per 256-thread
// block (10000 % 4 == 0 -> every block full, __syncthreads safe).
// Each warp: chunks of 32 edges, lane j computes exp(score) for edge j,
// shfl-broadcast, every lane gathers its 8 columns (uint4). Full chunks use a
// fixed-bound unroll-8 inner loop for 8 gathers in flight. Halves combined via
// shared memory; warp 0 of each pair divides and writes.
// ---------------------------------------------------------------------------
__global__ __launch_bounds__(256) void agg_kernel(const int* __restrict__ edges,
                                                  const __half* __restrict__ featsh,
                                                  const float* __restrict__ a1,
                                                  const float* __restrict__ a2,
                                                  const float* __restrict__ ba,
                                                  const int* __restrict__ rowptr,
                                                  float* __restrict__ out)
{
    __shared__ float racc[4][D];   // partial sums from half-1 warps
    __shared__ float dred[4];

    const int wid  = threadIdx.x >> 5;
    const int lane = threadIdx.x & 31;
    const int np   = wid >> 1;            // node slot in block: 0..3
    const int half = wid & 1;
    const int i    = blockIdx.x * 4 + np;

    const int ne0 = rowptr[i];
    const int ne1 = rowptr[i + 1];
    const int mid = ne0 + ((ne1 - ne0 + 1) >> 1);
    const int e0  = half ? mid : ne0;
    const int e1  = half ? ne1 : mid;

    const float a1i = a1[i] + ba[0];

    float acc[8] = {};
    float den = 0.f;

    int base = e0;
    // ---- full 32-edge chunks: fixed bounds -> unroll 8, 8 gathers in flight
    for (; base + 32 <= e1; base += 32) {
        const int idx = base + lane;
        const int d = edges[2 * idx + 1];
        float s = a1i + a2[d];
        s = (s > 0.f) ? s : (ALPHA * s);
        const float ex = expf(s);

        #pragma unroll 8
        for (int j = 0; j < 32; j++) {
            const float e = __shfl_sync(0xFFFFFFFFu, ex, j);
            const int  dd = __shfl_sync(0xFFFFFFFFu, d,  j);
            const uint4 v = *(const uint4*)(featsh + (size_t)dd * D + lane * 8);
            const float2 f0 = __half22float2(*(const __half2*)&v.x);
            const float2 f1 = __half22float2(*(const __half2*)&v.y);
            const float2 f2 = __half22float2(*(const __half2*)&v.z);
            const float2 f3 = __half22float2(*(const __half2*)&v.w);
            acc[0] += e * f0.x; acc[1] += e * f0.y;
            acc[2] += e * f1.x; acc[3] += e * f1.y;
            acc[4] += e * f2.x; acc[5] += e * f2.y;
            acc[6] += e * f3.x; acc[7] += e * f3.y;
            den    += e;
        }
    }
    // ---- remainder chunk ----
    if (base < e1) {
        const int idx = base + lane;
        const bool valid = (idx < e1);
        const int d = valid ? edges[2 * idx + 1] : 0;
        float ex = 0.f;
        if (valid) {
            float s = a1i + a2[d];
            s = (s > 0.f) ? s : (ALPHA * s);
            ex = expf(s);
        }
        const int cnt = e1 - base;
        #pragma unroll 4
        for (int j = 0; j < cnt; j++) {
            const float e = __shfl_sync(0xFFFFFFFFu, ex, j);
            const int  dd = __shfl_sync(0xFFFFFFFFu, d,  j);
            const uint4 v = *(const uint4*)(featsh + (size_t)dd * D + lane * 8);
            const float2 f0 = __half22float2(*(const __half2*)&v.x);
            const float2 f1 = __half22float2(*(const __half2*)&v.y);
            const float2 f2 = __half22float2(*(const __half2*)&v.z);
            const float2 f3 = __half22float2(*(const __half2*)&v.w);
            acc[0] += e * f0.x; acc[1] += e * f0.y;
            acc[2] += e * f1.x; acc[3] += e * f1.y;
            acc[4] += e * f2.x; acc[5] += e * f2.y;
            acc[6] += e * f3.x; acc[7] += e * f3.y;
            den    += e;
        }
    }

    // ---- combine halves via smem ----
    if (half == 1) {
        *(float4*)&racc[np][lane * 8]     = make_float4(acc[0], acc[1], acc[2], acc[3]);
        *(float4*)&racc[np][lane * 8 + 4] = make_float4(acc[4], acc[5], acc[6], acc[7]);
        if (lane == 0) dred[np] = den;
    }
    __syncthreads();

    if (half == 0) {
        const float4 p0 = *(const float4*)&racc[np][lane * 8];
        const float4 p1 = *(const float4*)&racc[np][lane * 8 + 4];
        const float dtot = den + dred[np];
        const float inv = (ne1 > ne0) ? (1.f / dtot) : 0.f;
        float4 o0 = make_float4((acc[0]+p0.x)*inv, (acc[1]+p0.y)*inv,
                                (acc[2]+p0.z)*inv, (acc[3]+p0.w)*inv);
        float4 o1 = make_float4((acc[4]+p1.x)*inv, (acc[5]+p1.y)*inv,
                                (acc[6]+p1.z)*inv, (acc[7]+p1.w)*inv);
        *(float4*)(out + (size_t)i * D + lane * 8)     = o0;
        *(float4*)(out + (size_t)i * D + lane * 8 + 4) = o1;
    }
}

// ---------------------------------------------------------------------------
extern "C" void kernel_launch(void* const* d_in, const int* in_sizes, int n_in,
                              void* d_out, int out_size)
{
    const float* X   = (const float*)d_in[0];
    const int*   edg = (const int*)d_in[1];
    const float* W1  = (const float*)d_in[2];
    const float* b1  = (const float*)d_in[3];
    const float* Wa  = (const float*)d_in[4];
    const float* ba  = (const float*)d_in[5];
    float*       out = (float*)d_out;

    __half* featsh; cudaGetSymbolAddress((void**)&featsh, g_feats_h);
    float*  a1;     cudaGetSymbolAddress((void**)&a1,     g_a1);
    float*  a2;     cudaGetSymbolAddress((void**)&a2,     g_a2);
    float*  u1;     cudaGetSymbolAddress((void**)&u1,     g_u1);
    float*  u2;     cudaGetSymbolAddress((void**)&u2,     g_u2);
    float*  c12;    cudaGetSymbolAddress((void**)&c12,    g_c12);
    int*    rowptr; cudaGetSymbolAddress((void**)&rowptr, g_rowptr);

    rowptr_kernel<<<(N_EDGES + 255) / 256, 256>>>(edg, rowptr);
    u_kernel<<<((D + 1) * 32 + 255) / 256, 256>>>(W1, b1, Wa, u1, u2, c12);

    dim3 ggrid(D / 64, (N_NODES + 127) / 128);   // 4 x 79 = 316 CTAs
    gemm_mma_kernel<<<ggrid, 256>>>(X, W1, b1, u1, u2, c12, featsh, a1, a2);

    agg_kernel<<<N_NODES / 4, 256>>>(edg, featsh, a1, a2, ba, rowptr, out);
}